// round 3
// baseline (speedup 1.0000x reference)
#include <cuda_runtime.h>
#include <math.h>

// Problem constants
#define BB   128
#define LW   400
#define SSL  30
#define VV   50000
#define EMB_ 128
#define HH   512
#define MMD  512
#define OOVN 30
#define VE   (VV + OOVN)   // 50030

// Output layout: concat of (final_dist, h_next, word_ctx, word_attn, p_gen, word_cov)
#define OUT_FINAL 0
#define OUT_H     (BB * VE)
#define OUT_WCTX  (OUT_H + BB * HH)
#define OUT_WATTN (OUT_WCTX + BB * MMD)
#define OUT_PGEN  (OUT_WATTN + BB * LW)
#define OUT_WCOV  (OUT_PGEN + BB)

typedef unsigned long long ull;

// packed f32x2 FMA: d = a*b + d  (two independent fp32 lanes per instruction)
__device__ __forceinline__ void ffma2(ull& d, ull a, ull b) {
    asm("fma.rn.f32x2 %0, %1, %2, %0;" : "+l"(d) : "l"(a), "l"(b));
}
__device__ __forceinline__ float pair_sum(ull v) {
    float2 p; *(ull*)&p = v; return p.x + p.y;
}

// -------------------- scratch (no allocations allowed) --------------------
__device__ float g_yemb[BB * EMB_];
__device__ float g_gi[BB * 3 * HH];
__device__ float g_gh[BB * 3 * HH];
__device__ float g_hlast[BB * HH];
__device__ float g_dpw[BB * HH];
__device__ float g_dps[BB * HH];
__device__ float g_wscores[BB * LW];
__device__ float g_sscores[BB * SSL];
__device__ float g_sattn[BB * SSL];
__device__ float g_cat[BB * 3 * HH];     // [word_ctx | sent_ctx | h_last]
__device__ float g_hid[BB * HH];
__device__ float g_pgen[BB];
__device__ float g_logits[(size_t)BB * VV];

// -------------------- embedding gather --------------------
__global__ void embed_kernel(const float* __restrict__ table, const int* __restrict__ y,
                             float* __restrict__ yemb) {
    int b = blockIdx.x, e = threadIdx.x;
    yemb[b * EMB_ + e] = table[(size_t)y[b] * EMB_ + e];
}

// ==================== f32x2 GEMM core ====================
// Tiles are stored k-major in smem: row-contiguous 16 k's per row. Accumulators
// are (even-k, odd-k) pairs; the pair lanes come directly from contiguous-k
// float4 loads so the inner loop is pure FFMA2 with no packing ops.

// C[M,N] = A[M,K] * W[N,K]^T + bias. 64x64 tile, 256 threads, 4x4 microtile.
__global__ void __launch_bounds__(256)
gemm_bias_kernel(const float* __restrict__ A, const float* __restrict__ W,
                 const float* __restrict__ bias, float* __restrict__ C,
                 int M, int N, int K) {
    __shared__ float As[64][20];   // [row][k], 16 k + pad
    __shared__ float Ws[64][20];
    int tid = threadIdx.x;
    int tx = tid & 15, ty = tid >> 4;
    int rb = blockIdx.y * 64, cb = blockIdx.x * 64;
    int lrow = tid >> 2, lq = tid & 3;
    ull acc[4][4] = {};

    for (int k0 = 0; k0 < K; k0 += 16) {
        float4 a4 = make_float4(0.f, 0.f, 0.f, 0.f);
        float4 w4 = make_float4(0.f, 0.f, 0.f, 0.f);
        if (rb + lrow < M) a4 = *(const float4*)&A[(size_t)(rb + lrow) * K + k0 + lq * 4];
        if (cb + lrow < N) w4 = *(const float4*)&W[(size_t)(cb + lrow) * K + k0 + lq * 4];
        *(float4*)&As[lrow][lq * 4] = a4;
        *(float4*)&Ws[lrow][lq * 4] = w4;
        __syncthreads();
#pragma unroll
        for (int kk = 0; kk < 4; kk++) {
            float4 av[4], wv[4];
#pragma unroll
            for (int i = 0; i < 4; i++) av[i] = *(const float4*)&As[ty * 4 + i][kk * 4];
#pragma unroll
            for (int j = 0; j < 4; j++) wv[j] = *(const float4*)&Ws[tx * 4 + j][kk * 4];
#pragma unroll
            for (int i = 0; i < 4; i++) {
                ull a0 = ((const ull*)&av[i])[0];
                ull a1 = ((const ull*)&av[i])[1];
#pragma unroll
                for (int j = 0; j < 4; j++) {
                    ffma2(acc[i][j], a0, ((const ull*)&wv[j])[0]);
                    ffma2(acc[i][j], a1, ((const ull*)&wv[j])[1]);
                }
            }
        }
        __syncthreads();
    }
#pragma unroll
    for (int i = 0; i < 4; i++) {
        int row = rb + ty * 4 + i;
        if (row >= M) continue;
#pragma unroll
        for (int j = 0; j < 4; j++) {
            int col = cb + tx * 4 + j;
            if (col < N) C[(size_t)row * N + col] = pair_sum(acc[i][j]) + (bias ? bias[col] : 0.f);
        }
    }
}

// -------------------- GRU combine (PyTorch gate layout r,z,n) --------------------
__global__ void gru_kernel(const float* __restrict__ gi, const float* __restrict__ gh,
                           const float* __restrict__ h0, float* __restrict__ hlast,
                           float* __restrict__ cat, float* __restrict__ out_h) {
    int idx = blockIdx.x * 256 + threadIdx.x;
    if (idx >= BB * HH) return;
    int b = idx / HH, j = idx % HH;
    const float* gib = gi + (size_t)b * 3 * HH;
    const float* ghb = gh + (size_t)b * 3 * HH;
    float ir = gib[j], iz = gib[HH + j], in_ = gib[2 * HH + j];
    float hr = ghb[j], hz = ghb[HH + j], hn = ghb[2 * HH + j];
    float r = 1.f / (1.f + expf(-(ir + hr)));
    float z = 1.f / (1.f + expf(-(iz + hz)));
    float n = tanhf(in_ + r * hn);
    float hl = (1.f - z) * n + z * h0[idx];
    hlast[idx] = hl;
    cat[(size_t)b * 1536 + 1024 + j] = hl;
    out_h[idx] = hl;
}

// -------------------- fused attention scores (f32x2 core) --------------------
// score[r] = sum_d v[d] * tanh( sum_m Wm[d,m]*mem[r,m] + dproj[b,d] (+ cov[r]*wcov[d]) )
template <bool HAS_COV>
__global__ void __launch_bounds__(256)
attn_scores_kernel(const float* __restrict__ mem, const float* __restrict__ Wm,
                   const float* __restrict__ dproj, const float* __restrict__ v,
                   const float* __restrict__ wcov, const float* __restrict__ cov,
                   float* __restrict__ scores, int Lper) {
    const int K = 512;
    __shared__ float As[64][20];
    __shared__ float Ws[64][20];
    int tid = threadIdx.x;
    int tx = tid & 15, ty = tid >> 4;
    int rowBase = blockIdx.x * 64;
    int lrow = tid >> 2, lq = tid & 3;

    float rowsum[4] = {0.f, 0.f, 0.f, 0.f};
    float covr[4];
    int bidx[4];
#pragma unroll
    for (int i = 0; i < 4; i++) {
        int r = rowBase + ty * 4 + i;
        bidx[i] = r / Lper;
        if (HAS_COV) covr[i] = cov[r];
    }

    for (int chunk = 0; chunk < 8; chunk++) {
        int col0 = chunk * 64;
        ull acc[4][4] = {};
        for (int k0 = 0; k0 < K; k0 += 16) {
            float4 a4 = *(const float4*)&mem[(size_t)(rowBase + lrow) * K + k0 + lq * 4];
            float4 w4 = *(const float4*)&Wm[(size_t)(col0 + lrow) * K + k0 + lq * 4];
            *(float4*)&As[lrow][lq * 4] = a4;
            *(float4*)&Ws[lrow][lq * 4] = w4;
            __syncthreads();
#pragma unroll
            for (int kk = 0; kk < 4; kk++) {
                float4 av[4], wv[4];
#pragma unroll
                for (int i = 0; i < 4; i++) av[i] = *(const float4*)&As[ty * 4 + i][kk * 4];
#pragma unroll
                for (int j = 0; j < 4; j++) wv[j] = *(const float4*)&Ws[tx * 4 + j][kk * 4];
#pragma unroll
                for (int i = 0; i < 4; i++) {
                    ull a0 = ((const ull*)&av[i])[0];
                    ull a1 = ((const ull*)&av[i])[1];
#pragma unroll
                    for (int j = 0; j < 4; j++) {
                        ffma2(acc[i][j], a0, ((const ull*)&wv[j])[0]);
                        ffma2(acc[i][j], a1, ((const ull*)&wv[j])[1]);
                    }
                }
            }
            __syncthreads();
        }
        // epilogue: tanh + v-weighted reduce over this chunk's 64 d's
#pragma unroll
        for (int j = 0; j < 4; j++) {
            int d = col0 + tx * 4 + j;
            float vd = v[d];
            float wc = HAS_COV ? wcov[d] : 0.f;
#pragma unroll
            for (int i = 0; i < 4; i++) {
                float f = pair_sum(acc[i][j]) + dproj[(size_t)bidx[i] * HH + d];
                if (HAS_COV) f += covr[i] * wc;
                rowsum[i] += tanhf(f) * vd;
            }
        }
    }
    // reduce across the 16 tx lanes (width-16 shfl groups == ty groups)
#pragma unroll
    for (int i = 0; i < 4; i++) {
        float s = rowsum[i];
#pragma unroll
        for (int off = 8; off > 0; off >>= 1) s += __shfl_down_sync(0xffffffffu, s, off, 16);
        if (tx == 0) scores[rowBase + ty * 4 + i] = s;
    }
}

// -------------------- softmax -> mask -> renormalize (+ coverage update) --------------------
__global__ void softmax_mask_kernel(const float* __restrict__ scores, const float* __restrict__ mask,
                                    const float* __restrict__ cov, float* __restrict__ attn_out,
                                    float* __restrict__ cov_out, int N) {
    __shared__ float buf[512];
    __shared__ float red[128];
    int b = blockIdx.x, tid = threadIdx.x;
    const float* s = scores + (size_t)b * N;
    float mx = -1e30f;
    for (int i = tid; i < N; i += 128) { float vv = s[i]; buf[i] = vv; mx = fmaxf(mx, vv); }
    red[tid] = mx; __syncthreads();
    for (int off = 64; off; off >>= 1) { if (tid < off) red[tid] = fmaxf(red[tid], red[tid + off]); __syncthreads(); }
    mx = red[0]; __syncthreads();
    float sum = 0.f;
    for (int i = tid; i < N; i += 128) { float e = expf(buf[i] - mx); buf[i] = e; sum += e; }
    red[tid] = sum; __syncthreads();
    for (int off = 64; off; off >>= 1) { if (tid < off) red[tid] += red[tid + off]; __syncthreads(); }
    sum = red[0]; __syncthreads();
    float s2 = 0.f;
    for (int i = tid; i < N; i += 128) { float t = (buf[i] / sum) * mask[(size_t)b * N + i]; buf[i] = t; s2 += t; }
    red[tid] = s2; __syncthreads();
    for (int off = 64; off; off >>= 1) { if (tid < off) red[tid] += red[tid + off]; __syncthreads(); }
    s2 = red[0];
    float inv = 1.f / (s2 + 1e-10f);
    for (int i = tid; i < N; i += 128) {
        float a = buf[i] * inv;
        attn_out[(size_t)b * N + i] = a;
        if (cov_out) cov_out[(size_t)b * N + i] = cov[(size_t)b * N + i] + a;
    }
}

// -------------------- context: ctx[b,m] = sum_l attn[b,l] * mem[b,l,m] --------------------
__global__ void context_kernel(const float* __restrict__ attn, const float* __restrict__ mem,
                               float* __restrict__ ctx_out, float* __restrict__ cat,
                               int Lc, int catOff) {
    __shared__ float a_s[512];
    int b = blockIdx.x;
    int m = blockIdx.y * 128 + threadIdx.x;
    for (int i = threadIdx.x; i < Lc; i += 128) a_s[i] = attn[(size_t)b * Lc + i];
    __syncthreads();
    const float* mb = mem + (size_t)b * Lc * MMD + m;
    float acc = 0.f;
#pragma unroll 8
    for (int l = 0; l < Lc; l++) acc += a_s[l] * mb[(size_t)l * MMD];
    if (ctx_out) ctx_out[(size_t)b * MMD + m] = acc;
    cat[(size_t)b * 1536 + catOff + m] = acc;
}

// -------------------- p_gen --------------------
__global__ void pgen_kernel(const float* __restrict__ cat, const float* __restrict__ yemb,
                            const float* __restrict__ pw, const float* __restrict__ pb,
                            float* __restrict__ pg_scr, float* __restrict__ pg_out) {
    __shared__ float red[256];
    int b = blockIdx.x, tid = threadIdx.x;
    float s = 0.f;
    for (int i = tid; i < 1536; i += 256) s += cat[(size_t)b * 1536 + i] * pw[i];
    for (int i = tid; i < EMB_; i += 256) s += yemb[(size_t)b * EMB_ + i] * pw[1536 + i];
    red[tid] = s; __syncthreads();
    for (int off = 128; off; off >>= 1) { if (tid < off) red[tid] += red[tid + off]; __syncthreads(); }
    if (tid == 0) {
        float p = 1.f / (1.f + expf(-(red[0] + pb[0])));
        pg_scr[b] = p;
        pg_out[b] = p;
    }
}

// -------------------- vocab softmax + p_gen mix + OOV scatter (row-private) --------------------
__global__ void final_kernel(const float* __restrict__ logits, const float* __restrict__ pgen,
                             const float* __restrict__ wattn, const int* __restrict__ src_oov,
                             float* __restrict__ out_final) {
    __shared__ float red[256];
    int b = blockIdx.x, tid = threadIdx.x;
    const float* lg = logits + (size_t)b * VV;
    float mx = -1e30f;
    for (int i = tid; i < VV; i += 256) mx = fmaxf(mx, lg[i]);
    red[tid] = mx; __syncthreads();
    for (int off = 128; off; off >>= 1) { if (tid < off) red[tid] = fmaxf(red[tid], red[tid + off]); __syncthreads(); }
    mx = red[0]; __syncthreads();
    float sum = 0.f;
    for (int i = tid; i < VV; i += 256) sum += expf(lg[i] - mx);
    red[tid] = sum; __syncthreads();
    for (int off = 128; off; off >>= 1) { if (tid < off) red[tid] += red[tid + off]; __syncthreads(); }
    sum = red[0];
    float pg = pgen[b];
    float scale = pg / sum;
    float* fr = out_final + (size_t)b * VE;
    for (int i = tid; i < VV; i += 256) fr[i] = expf(lg[i] - mx) * scale;
    for (int i = VV + tid; i < VE; i += 256) fr[i] = 0.f;
    __syncthreads();
    float om = 1.f - pg;
    for (int l = tid; l < LW; l += 256) {
        int idx = src_oov[(size_t)b * LW + l];
        atomicAdd(&fr[idx], om * wattn[(size_t)b * LW + l]);
    }
}

// -------------------- launcher --------------------
extern "C" void kernel_launch(void* const* d_in, const int* in_sizes, int n_in,
                              void* d_out, int out_size) {
    (void)in_sizes; (void)n_in; (void)out_size;
    const float* h0   = (const float*)d_in[0];
    const float* wmem = (const float*)d_in[1];
    const float* smem_bank = (const float*)d_in[2];
    const float* wmask = (const float*)d_in[3];
    const float* smask = (const float*)d_in[4];
    const float* cov   = (const float*)d_in[5];
    const float* emb   = (const float*)d_in[6];
    const float* gwih  = (const float*)d_in[7];
    const float* gwhh  = (const float*)d_in[8];
    const float* gbih  = (const float*)d_in[9];
    const float* gbhh  = (const float*)d_in[10];
    const float* wmp   = (const float*)d_in[11];
    const float* wdpw  = (const float*)d_in[12];
    const float* wdpb  = (const float*)d_in[13];
    const float* wv    = (const float*)d_in[14];
    const float* wcp   = (const float*)d_in[15];
    const float* smp   = (const float*)d_in[16];
    const float* sdpw  = (const float*)d_in[17];
    const float* sdpb  = (const float*)d_in[18];
    const float* sv    = (const float*)d_in[19];
    const float* pgw   = (const float*)d_in[20];
    const float* pgb   = (const float*)d_in[21];
    const float* vd1w  = (const float*)d_in[22];
    const float* vd1b  = (const float*)d_in[23];
    const float* vd2w  = (const float*)d_in[24];
    const float* vd2b  = (const float*)d_in[25];
    const int*   y     = (const int*)d_in[26];
    const int*   soov  = (const int*)d_in[27];
    float* out = (float*)d_out;

    float *yemb, *gi, *gh, *hl, *dpw, *dps, *wsc, *ssc, *sat, *cat, *hid, *pg, *lg;
    cudaGetSymbolAddress((void**)&yemb, g_yemb);
    cudaGetSymbolAddress((void**)&gi,   g_gi);
    cudaGetSymbolAddress((void**)&gh,   g_gh);
    cudaGetSymbolAddress((void**)&hl,   g_hlast);
    cudaGetSymbolAddress((void**)&dpw,  g_dpw);
    cudaGetSymbolAddress((void**)&dps,  g_dps);
    cudaGetSymbolAddress((void**)&wsc,  g_wscores);
    cudaGetSymbolAddress((void**)&ssc,  g_sscores);
    cudaGetSymbolAddress((void**)&sat,  g_sattn);
    cudaGetSymbolAddress((void**)&cat,  g_cat);
    cudaGetSymbolAddress((void**)&hid,  g_hid);
    cudaGetSymbolAddress((void**)&pg,   g_pgen);
    cudaGetSymbolAddress((void**)&lg,   g_logits);

    // 1. embedding + GRU gates + combine
    embed_kernel<<<BB, EMB_>>>(emb, y, yemb);
    gemm_bias_kernel<<<dim3(24, 2), 256>>>(yemb, gwih, gbih, gi, BB, 3 * HH, EMB_);
    gemm_bias_kernel<<<dim3(24, 2), 256>>>(h0,   gwhh, gbhh, gh, BB, 3 * HH, HH);
    gru_kernel<<<(BB * HH + 255) / 256, 256>>>(gi, gh, h0, hl, cat, out + OUT_H);

    // 2. decoder-state projections for both attentions
    gemm_bias_kernel<<<dim3(8, 2), 256>>>(hl, wdpw, wdpb, dpw, BB, HH, HH);
    gemm_bias_kernel<<<dim3(8, 2), 256>>>(hl, sdpw, sdpb, dps, BB, HH, HH);

    // 3. fused attention scores
    attn_scores_kernel<true ><<<(BB * LW) / 64, 256>>>(wmem, wmp, dpw, wv, wcp, cov, wsc, LW);
    attn_scores_kernel<false><<<(BB * SSL) / 64, 256>>>(smem_bank, smp, dps, sv, nullptr, nullptr, ssc, SSL);

    // 4. softmax + mask + renorm (+ coverage output for word)
    softmax_mask_kernel<<<BB, 128>>>(wsc, wmask, cov, out + OUT_WATTN, out + OUT_WCOV, LW);
    softmax_mask_kernel<<<BB, 128>>>(ssc, smask, nullptr, sat, nullptr, SSL);

    // 5. contexts (into cat buffer; word_ctx also to output)
    context_kernel<<<dim3(BB, 4), 128>>>(out + OUT_WATTN, wmem, out + OUT_WCTX, cat, LW, 0);
    context_kernel<<<dim3(BB, 4), 128>>>(sat, smem_bank, nullptr, cat, SSL, 512);

    // 6. p_gen
    pgen_kernel<<<BB, 256>>>(cat, yemb, pgw, pgb, pg, out + OUT_PGEN);

    // 7. vocab head: hid then logits
    gemm_bias_kernel<<<dim3(8, 2), 256>>>(cat, vd1w, vd1b, hid, BB, HH, 3 * HH);
    gemm_bias_kernel<<<dim3((VV + 63) / 64, 2), 256>>>(hid, vd2w, vd2b, lg, BB, VV, HH);

    // 8. vocab softmax, p_gen mix, zeros for OOV slots, scatter-add of copy dist
    final_kernel<<<BB, 256>>>(lg, pg, out + OUT_WATTN, soov, out + OUT_FINAL);
}

// round 6
// speedup vs baseline: 3.1001x; 3.1001x over previous
#include <cuda_runtime.h>
#include <cuda_bf16.h>
#include <math.h>

// Problem constants
#define BB   128
#define LW   400
#define SSL  30
#define VV   50000
#define EMB_ 128
#define HH   512
#define MMD  512
#define OOVN 30
#define VE   (VV + OOVN)   // 50030

// Output layout: concat of (final_dist, h_next, word_ctx, word_attn, p_gen, word_cov)
#define OUT_FINAL 0
#define OUT_H     (BB * VE)
#define OUT_WCTX  (OUT_H + BB * HH)
#define OUT_WATTN (OUT_WCTX + BB * MMD)
#define OUT_PGEN  (OUT_WATTN + BB * LW)
#define OUT_WCOV  (OUT_PGEN + BB)

#define SPITCH 40   // smem bf16 row pitch (conflict-free for fills + frags)

// -------------------- scratch (no allocations allowed) --------------------
__device__ float g_yemb[BB * EMB_];
__device__ float g_gi[BB * 3 * HH];
__device__ float g_gh[BB * 3 * HH];
__device__ float g_hlast[BB * HH];
__device__ float g_dpw[BB * HH];
__device__ float g_dps[BB * HH];
__device__ float g_wscores[BB * LW];
__device__ float g_sscores[BB * SSL];
__device__ float g_sattn[BB * SSL];
__device__ float g_cat[BB * 3 * HH];     // [word_ctx | sent_ctx | h_last]
__device__ float g_hid[BB * HH];
__device__ float g_pgen[BB];
__device__ float g_logits[(size_t)BB * VV];

// -------------------- helpers --------------------
__device__ __forceinline__ unsigned pack_bf2(__nv_bfloat16 a, __nv_bfloat16 b) {
    __nv_bfloat162 t(a, b);
    return *(unsigned*)&t;
}
// split fp32 -> (hi, lo) bf16 pair; x ≈ hi + lo with |lo| <= 2^-9 |x|
__device__ __forceinline__ void split2(float x, float y, unsigned& hi2, unsigned& lo2) {
    __nv_bfloat16 hx = __float2bfloat16_rn(x);
    __nv_bfloat16 hy = __float2bfloat16_rn(y);
    __nv_bfloat16 lx = __float2bfloat16_rn(x - __bfloat162float(hx));
    __nv_bfloat16 ly = __float2bfloat16_rn(y - __bfloat162float(hy));
    hi2 = pack_bf2(hx, hy);
    lo2 = pack_bf2(lx, ly);
}

__device__ __forceinline__ void mma_bf16(float* c, const unsigned* a, const unsigned* b) {
    asm volatile(
        "mma.sync.aligned.m16n8k16.row.col.f32.bf16.bf16.f32 "
        "{%0,%1,%2,%3}, {%4,%5,%6,%7}, {%8,%9}, {%0,%1,%2,%3};"
        : "+f"(c[0]), "+f"(c[1]), "+f"(c[2]), "+f"(c[3])
        : "r"(a[0]), "r"(a[1]), "r"(a[2]), "r"(a[3]), "r"(b[0]), "r"(b[1]));
}

// -------------------- embedding gather --------------------
__global__ void embed_kernel(const float* __restrict__ table, const int* __restrict__ y,
                             float* __restrict__ yemb) {
    int b = blockIdx.x, e = threadIdx.x;
    yemb[b * EMB_ + e] = table[(size_t)y[b] * EMB_ + e];
}

// -------------------- scalar SGEMM (small GEMMs): C[M,N] = A[M,K]*W[N,K]^T + bias --------------------
__global__ void gemm_bias_kernel(const float* __restrict__ A, const float* __restrict__ W,
                                 const float* __restrict__ bias, float* __restrict__ C,
                                 int M, int N, int K) {
    __shared__ float As[16][68];   // [k][m], padded
    __shared__ float Ws[16][68];   // [k][n], padded
    int tid = threadIdx.x;
    int tx = tid & 15, ty = tid >> 4;
    int rb = blockIdx.y * 64, cb = blockIdx.x * 64;
    int lr = tid >> 2, kq = tid & 3;
    float acc[4][4] = {};

    for (int k0 = 0; k0 < K; k0 += 16) {
        float4 a4 = make_float4(0.f, 0.f, 0.f, 0.f);
        float4 w4 = make_float4(0.f, 0.f, 0.f, 0.f);
        if (rb + lr < M) a4 = *(const float4*)&A[(size_t)(rb + lr) * K + k0 + kq * 4];
        if (cb + lr < N) w4 = *(const float4*)&W[(size_t)(cb + lr) * K + k0 + kq * 4];
        As[kq * 4 + 0][lr] = a4.x; As[kq * 4 + 1][lr] = a4.y;
        As[kq * 4 + 2][lr] = a4.z; As[kq * 4 + 3][lr] = a4.w;
        Ws[kq * 4 + 0][lr] = w4.x; Ws[kq * 4 + 1][lr] = w4.y;
        Ws[kq * 4 + 2][lr] = w4.z; Ws[kq * 4 + 3][lr] = w4.w;
        __syncthreads();
#pragma unroll
        for (int kk = 0; kk < 16; kk++) {
            float4 a = *(const float4*)&As[kk][ty * 4];
            float4 w = *(const float4*)&Ws[kk][tx * 4];
            acc[0][0] += a.x * w.x; acc[0][1] += a.x * w.y; acc[0][2] += a.x * w.z; acc[0][3] += a.x * w.w;
            acc[1][0] += a.y * w.x; acc[1][1] += a.y * w.y; acc[1][2] += a.y * w.z; acc[1][3] += a.y * w.w;
            acc[2][0] += a.z * w.x; acc[2][1] += a.z * w.y; acc[2][2] += a.z * w.z; acc[2][3] += a.z * w.w;
            acc[3][0] += a.w * w.x; acc[3][1] += a.w * w.y; acc[3][2] += a.w * w.z; acc[3][3] += a.w * w.w;
        }
        __syncthreads();
    }
#pragma unroll
    for (int i = 0; i < 4; i++) {
        int row = rb + ty * 4 + i;
        if (row >= M) continue;
#pragma unroll
        for (int j = 0; j < 4; j++) {
            int col = cb + tx * 4 + j;
            if (col < N) C[(size_t)row * N + col] = acc[i][j] + (bias ? bias[col] : 0.f);
        }
    }
}

// ==================== bf16x3 tensor-core GEMM (vocab logits) ====================
// C[M,N] = A[M,K] * W[N,K]^T + bias, split-precision: hi*hi + hi*lo + lo*hi.
__global__ void __launch_bounds__(256)
mma_gemm_bias(const float* __restrict__ A, const float* __restrict__ W,
              const float* __restrict__ bias, float* __restrict__ C,
              int M, int N, int K) {
    __shared__ __nv_bfloat16 Ah[64][SPITCH], Al[64][SPITCH];
    __shared__ __nv_bfloat16 Wh[64][SPITCH], Wl[64][SPITCH];
    int tid = threadIdx.x;
    int wid = tid >> 5, lane = tid & 31;
    int warpM = wid & 3, warpN = wid >> 2;          // 4x2 warps
    int warpRow = warpM * 16, warpCol = warpN * 32;
    int g = lane >> 2, tg = lane & 3;
    int rb = blockIdx.y * 64, cb = blockIdx.x * 64;
    int lrow = tid >> 2, lq = tid & 3;

    float acc[4][4] = {};

    for (int k0 = 0; k0 < K; k0 += 16) {
        __syncthreads();
        float4 a4 = make_float4(0.f, 0.f, 0.f, 0.f);
        float4 w4 = make_float4(0.f, 0.f, 0.f, 0.f);
        if (rb + lrow < M) a4 = *(const float4*)&A[(size_t)(rb + lrow) * K + k0 + lq * 4];
        if (cb + lrow < N) w4 = *(const float4*)&W[(size_t)(cb + lrow) * K + k0 + lq * 4];
        unsigned h0, l0, h1, l1;
        split2(a4.x, a4.y, h0, l0); split2(a4.z, a4.w, h1, l1);
        *(unsigned*)&Ah[lrow][lq * 4] = h0; *(unsigned*)&Ah[lrow][lq * 4 + 2] = h1;
        *(unsigned*)&Al[lrow][lq * 4] = l0; *(unsigned*)&Al[lrow][lq * 4 + 2] = l1;
        split2(w4.x, w4.y, h0, l0); split2(w4.z, w4.w, h1, l1);
        *(unsigned*)&Wh[lrow][lq * 4] = h0; *(unsigned*)&Wh[lrow][lq * 4 + 2] = h1;
        *(unsigned*)&Wl[lrow][lq * 4] = l0; *(unsigned*)&Wl[lrow][lq * 4 + 2] = l1;
        __syncthreads();

        unsigned ah[4], al[4];
        ah[0] = *(unsigned*)&Ah[warpRow + g][tg * 2];
        ah[1] = *(unsigned*)&Ah[warpRow + g + 8][tg * 2];
        ah[2] = *(unsigned*)&Ah[warpRow + g][tg * 2 + 8];
        ah[3] = *(unsigned*)&Ah[warpRow + g + 8][tg * 2 + 8];
        al[0] = *(unsigned*)&Al[warpRow + g][tg * 2];
        al[1] = *(unsigned*)&Al[warpRow + g + 8][tg * 2];
        al[2] = *(unsigned*)&Al[warpRow + g][tg * 2 + 8];
        al[3] = *(unsigned*)&Al[warpRow + g + 8][tg * 2 + 8];
#pragma unroll
        for (int nb = 0; nb < 4; nb++) {
            int wc = warpCol + nb * 8 + g;
            unsigned bh[2], bl[2];
            bh[0] = *(unsigned*)&Wh[wc][tg * 2];
            bh[1] = *(unsigned*)&Wh[wc][tg * 2 + 8];
            bl[0] = *(unsigned*)&Wl[wc][tg * 2];
            bl[1] = *(unsigned*)&Wl[wc][tg * 2 + 8];
            mma_bf16(acc[nb], ah, bh);
            mma_bf16(acc[nb], ah, bl);
            mma_bf16(acc[nb], al, bh);
        }
    }

#pragma unroll
    for (int nb = 0; nb < 4; nb++) {
        int col = cb + warpCol + nb * 8 + tg * 2;
        int r0 = rb + warpRow + g, r1 = r0 + 8;
        if (col < N) {
            float bs = bias ? bias[col] : 0.f;
            if (r0 < M) C[(size_t)r0 * N + col] = acc[nb][0] + bs;
            if (r1 < M) C[(size_t)r1 * N + col] = acc[nb][2] + bs;
        }
        if (col + 1 < N) {
            float bs = bias ? bias[col + 1] : 0.f;
            if (r0 < M) C[(size_t)r0 * N + col + 1] = acc[nb][1] + bs;
            if (r1 < M) C[(size_t)r1 * N + col + 1] = acc[nb][3] + bs;
        }
    }
}

// ==================== fused attention scores (bf16x3 tensor core) ====================
// score[r] = sum_d v[d] * tanh( sum_m Wm[d,m]*mem[r,m] + dproj[b,d] (+ cov[r]*wcov[d]) )
template <bool HAS_COV>
__global__ void __launch_bounds__(256)
attn_scores_mma(const float* __restrict__ mem, const float* __restrict__ Wm,
                const float* __restrict__ dproj, const float* __restrict__ v,
                const float* __restrict__ wcov, const float* __restrict__ cov,
                float* __restrict__ scores, int Lper) {
    const int K = 512;
    __shared__ __nv_bfloat16 Ah[64][SPITCH], Al[64][SPITCH];
    __shared__ __nv_bfloat16 Wh[64][SPITCH], Wl[64][SPITCH];
    __shared__ float rowred[64];

    int tid = threadIdx.x;
    int wid = tid >> 5, lane = tid & 31;
    int warpM = wid & 3, warpN = wid >> 2;          // 4x2
    int warpRow = warpM * 16, warpCol = warpN * 32;
    int g = lane >> 2, tg = lane & 3;
    int rowBase = blockIdx.x * 64;
    int lrow = tid >> 2, lq = tid & 3;

    if (tid < 64) rowred[tid] = 0.f;

    int r0 = rowBase + warpRow + g, r1 = r0 + 8;
    int b0 = r0 / Lper, b1 = r1 / Lper;
    float cov0 = 0.f, cov1 = 0.f;
    if (HAS_COV) { cov0 = cov[r0]; cov1 = cov[r1]; }
    float rs0 = 0.f, rs1 = 0.f;

    for (int chunk = 0; chunk < 8; chunk++) {
        int col0 = chunk * 64;
        float acc[4][4] = {};
        for (int k0 = 0; k0 < K; k0 += 16) {
            __syncthreads();
            float4 a4 = *(const float4*)&mem[(size_t)(rowBase + lrow) * K + k0 + lq * 4];
            float4 w4 = *(const float4*)&Wm[(size_t)(col0 + lrow) * K + k0 + lq * 4];
            unsigned h0, l0, h1, l1;
            split2(a4.x, a4.y, h0, l0); split2(a4.z, a4.w, h1, l1);
            *(unsigned*)&Ah[lrow][lq * 4] = h0; *(unsigned*)&Ah[lrow][lq * 4 + 2] = h1;
            *(unsigned*)&Al[lrow][lq * 4] = l0; *(unsigned*)&Al[lrow][lq * 4 + 2] = l1;
            split2(w4.x, w4.y, h0, l0); split2(w4.z, w4.w, h1, l1);
            *(unsigned*)&Wh[lrow][lq * 4] = h0; *(unsigned*)&Wh[lrow][lq * 4 + 2] = h1;
            *(unsigned*)&Wl[lrow][lq * 4] = l0; *(unsigned*)&Wl[lrow][lq * 4 + 2] = l1;
            __syncthreads();

            unsigned ah[4], al[4];
            ah[0] = *(unsigned*)&Ah[warpRow + g][tg * 2];
            ah[1] = *(unsigned*)&Ah[warpRow + g + 8][tg * 2];
            ah[2] = *(unsigned*)&Ah[warpRow + g][tg * 2 + 8];
            ah[3] = *(unsigned*)&Ah[warpRow + g + 8][tg * 2 + 8];
            al[0] = *(unsigned*)&Al[warpRow + g][tg * 2];
            al[1] = *(unsigned*)&Al[warpRow + g + 8][tg * 2];
            al[2] = *(unsigned*)&Al[warpRow + g][tg * 2 + 8];
            al[3] = *(unsigned*)&Al[warpRow + g + 8][tg * 2 + 8];
#pragma unroll
            for (int nb = 0; nb < 4; nb++) {
                int wc = warpCol + nb * 8 + g;
                unsigned bh[2], bl[2];
                bh[0] = *(unsigned*)&Wh[wc][tg * 2];
                bh[1] = *(unsigned*)&Wh[wc][tg * 2 + 8];
                bl[0] = *(unsigned*)&Wl[wc][tg * 2];
                bl[1] = *(unsigned*)&Wl[wc][tg * 2 + 8];
                mma_bf16(acc[nb], ah, bh);
                mma_bf16(acc[nb], ah, bl);
                mma_bf16(acc[nb], al, bh);
            }
        }
        // epilogue for this chunk's 64 d-columns
#pragma unroll
        for (int nb = 0; nb < 4; nb++) {
            int d = col0 + warpCol + nb * 8 + tg * 2;
#pragma unroll
            for (int jj = 0; jj < 2; jj++) {
                int dd = d + jj;
                float vd = v[dd];
                float wc = HAS_COV ? wcov[dd] : 0.f;
                float f0 = acc[nb][jj] + dproj[(size_t)b0 * HH + dd];
                float f1 = acc[nb][2 + jj] + dproj[(size_t)b1 * HH + dd];
                if (HAS_COV) { f0 += cov0 * wc; f1 += cov1 * wc; }
                rs0 += tanhf(f0) * vd;
                rs1 += tanhf(f1) * vd;
            }
        }
    }
    // reduce over the 4 tg lanes
    rs0 += __shfl_xor_sync(0xffffffffu, rs0, 1);
    rs0 += __shfl_xor_sync(0xffffffffu, rs0, 2);
    rs1 += __shfl_xor_sync(0xffffffffu, rs1, 1);
    rs1 += __shfl_xor_sync(0xffffffffu, rs1, 2);
    if (tg == 0) {
        atomicAdd(&rowred[warpRow + g], rs0);
        atomicAdd(&rowred[warpRow + g + 8], rs1);
    }
    __syncthreads();
    if (tid < 64) scores[rowBase + tid] = rowred[tid];
}

// -------------------- GRU combine (PyTorch gate layout r,z,n) --------------------
__global__ void gru_kernel(const float* __restrict__ gi, const float* __restrict__ gh,
                           const float* __restrict__ h0, float* __restrict__ hlast,
                           float* __restrict__ cat, float* __restrict__ out_h) {
    int idx = blockIdx.x * 256 + threadIdx.x;
    if (idx >= BB * HH) return;
    int b = idx / HH, j = idx % HH;
    const float* gib = gi + (size_t)b * 3 * HH;
    const float* ghb = gh + (size_t)b * 3 * HH;
    float ir = gib[j], iz = gib[HH + j], in_ = gib[2 * HH + j];
    float hr = ghb[j], hz = ghb[HH + j], hn = ghb[2 * HH + j];
    float r = 1.f / (1.f + expf(-(ir + hr)));
    float z = 1.f / (1.f + expf(-(iz + hz)));
    float n = tanhf(in_ + r * hn);
    float hl = (1.f - z) * n + z * h0[idx];
    hlast[idx] = hl;
    cat[(size_t)b * 1536 + 1024 + j] = hl;
    out_h[idx] = hl;
}

// -------------------- softmax -> mask -> renormalize (+ coverage update) --------------------
__global__ void softmax_mask_kernel(const float* __restrict__ scores, const float* __restrict__ mask,
                                    const float* __restrict__ cov, float* __restrict__ attn_out,
                                    float* __restrict__ cov_out, int N) {
    __shared__ float buf[512];
    __shared__ float red[128];
    int b = blockIdx.x, tid = threadIdx.x;
    const float* s = scores + (size_t)b * N;
    float mx = -1e30f;
    for (int i = tid; i < N; i += 128) { float vv = s[i]; buf[i] = vv; mx = fmaxf(mx, vv); }
    red[tid] = mx; __syncthreads();
    for (int off = 64; off; off >>= 1) { if (tid < off) red[tid] = fmaxf(red[tid], red[tid + off]); __syncthreads(); }
    mx = red[0]; __syncthreads();
    float sum = 0.f;
    for (int i = tid; i < N; i += 128) { float e = expf(buf[i] - mx); buf[i] = e; sum += e; }
    red[tid] = sum; __syncthreads();
    for (int off = 64; off; off >>= 1) { if (tid < off) red[tid] += red[tid + off]; __syncthreads(); }
    sum = red[0]; __syncthreads();
    float s2 = 0.f;
    for (int i = tid; i < N; i += 128) { float t = (buf[i] / sum) * mask[(size_t)b * N + i]; buf[i] = t; s2 += t; }
    red[tid] = s2; __syncthreads();
    for (int off = 64; off; off >>= 1) { if (tid < off) red[tid] += red[tid + off]; __syncthreads(); }
    s2 = red[0];
    float inv = 1.f / (s2 + 1e-10f);
    for (int i = tid; i < N; i += 128) {
        float a = buf[i] * inv;
        attn_out[(size_t)b * N + i] = a;
        if (cov_out) cov_out[(size_t)b * N + i] = cov[(size_t)b * N + i] + a;
    }
}

// -------------------- context: ctx[b,m] = sum_l attn[b,l] * mem[b,l,m] --------------------
__global__ void context_kernel(const float* __restrict__ attn, const float* __restrict__ mem,
                               float* __restrict__ ctx_out, float* __restrict__ cat,
                               int Lc, int catOff) {
    __shared__ float a_s[512];
    int b = blockIdx.x;
    int m = blockIdx.y * 128 + threadIdx.x;
    for (int i = threadIdx.x; i < Lc; i += 128) a_s[i] = attn[(size_t)b * Lc + i];
    __syncthreads();
    const float* mb = mem + (size_t)b * Lc * MMD + m;
    float acc = 0.f;
#pragma unroll 4
    for (int l = 0; l < Lc; l++) acc += a_s[l] * mb[(size_t)l * MMD];
    if (ctx_out) ctx_out[(size_t)b * MMD + m] = acc;
    cat[(size_t)b * 1536 + catOff + m] = acc;
}

// -------------------- p_gen --------------------
__global__ void pgen_kernel(const float* __restrict__ cat, const float* __restrict__ yemb,
                            const float* __restrict__ pw, const float* __restrict__ pb,
                            float* __restrict__ pg_scr, float* __restrict__ pg_out) {
    __shared__ float red[256];
    int b = blockIdx.x, tid = threadIdx.x;
    float s = 0.f;
    for (int i = tid; i < 1536; i += 256) s += cat[(size_t)b * 1536 + i] * pw[i];
    for (int i = tid; i < EMB_; i += 256) s += yemb[(size_t)b * EMB_ + i] * pw[1536 + i];
    red[tid] = s; __syncthreads();
    for (int off = 128; off; off >>= 1) { if (tid < off) red[tid] += red[tid + off]; __syncthreads(); }
    if (tid == 0) {
        float p = 1.f / (1.f + expf(-(red[0] + pb[0])));
        pg_scr[b] = p;
        pg_out[b] = p;
    }
}

// -------------------- vocab softmax + p_gen mix + OOV scatter (row-private) --------------------
__global__ void final_kernel(const float* __restrict__ logits, const float* __restrict__ pgen,
                             const float* __restrict__ wattn, const int* __restrict__ src_oov,
                             float* __restrict__ out_final) {
    __shared__ float red[256];
    int b = blockIdx.x, tid = threadIdx.x;
    const float* lg = logits + (size_t)b * VV;
    float mx = -1e30f;
    for (int i = tid; i < VV; i += 256) mx = fmaxf(mx, lg[i]);
    red[tid] = mx; __syncthreads();
    for (int off = 128; off; off >>= 1) { if (tid < off) red[tid] = fmaxf(red[tid], red[tid + off]); __syncthreads(); }
    mx = red[0]; __syncthreads();
    float sum = 0.f;
    for (int i = tid; i < VV; i += 256) sum += expf(lg[i] - mx);
    red[tid] = sum; __syncthreads();
    for (int off = 128; off; off >>= 1) { if (tid < off) red[tid] += red[tid + off]; __syncthreads(); }
    sum = red[0];
    float pg = pgen[b];
    float scale = pg / sum;
    float* fr = out_final + (size_t)b * VE;
    for (int i = tid; i < VV; i += 256) fr[i] = expf(lg[i] - mx) * scale;
    for (int i = VV + tid; i < VE; i += 256) fr[i] = 0.f;
    __syncthreads();
    float om = 1.f - pg;
    for (int l = tid; l < LW; l += 256) {
        int idx = src_oov[(size_t)b * LW + l];
        atomicAdd(&fr[idx], om * wattn[(size_t)b * LW + l]);
    }
}

// -------------------- launcher --------------------
extern "C" void kernel_launch(void* const* d_in, const int* in_sizes, int n_in,
                              void* d_out, int out_size) {
    (void)in_sizes; (void)n_in; (void)out_size;
    const float* h0   = (const float*)d_in[0];
    const float* wmem = (const float*)d_in[1];
    const float* smem_bank = (const float*)d_in[2];
    const float* wmask = (const float*)d_in[3];
    const float* smask = (const float*)d_in[4];
    const float* cov   = (const float*)d_in[5];
    const float* emb   = (const float*)d_in[6];
    const float* gwih  = (const float*)d_in[7];
    const float* gwhh  = (const float*)d_in[8];
    const float* gbih  = (const float*)d_in[9];
    const float* gbhh  = (const float*)d_in[10];
    const float* wmp   = (const float*)d_in[11];
    const float* wdpw  = (const float*)d_in[12];
    const float* wdpb  = (const float*)d_in[13];
    const float* wv    = (const float*)d_in[14];
    const float* wcp   = (const float*)d_in[15];
    const float* smp   = (const float*)d_in[16];
    const float* sdpw  = (const float*)d_in[17];
    const float* sdpb  = (const float*)d_in[18];
    const float* sv    = (const float*)d_in[19];
    const float* pgw   = (const float*)d_in[20];
    const float* pgb   = (const float*)d_in[21];
    const float* vd1w  = (const float*)d_in[22];
    const float* vd1b  = (const float*)d_in[23];
    const float* vd2w  = (const float*)d_in[24];
    const float* vd2b  = (const float*)d_in[25];
    const int*   y     = (const int*)d_in[26];
    const int*   soov  = (const int*)d_in[27];
    float* out = (float*)d_out;

    float *yemb, *gi, *gh, *hl, *dpw, *dps, *wsc, *ssc, *sat, *cat, *hid, *pg, *lg;
    cudaGetSymbolAddress((void**)&yemb, g_yemb);
    cudaGetSymbolAddress((void**)&gi,   g_gi);
    cudaGetSymbolAddress((void**)&gh,   g_gh);
    cudaGetSymbolAddress((void**)&hl,   g_hlast);
    cudaGetSymbolAddress((void**)&dpw,  g_dpw);
    cudaGetSymbolAddress((void**)&dps,  g_dps);
    cudaGetSymbolAddress((void**)&wsc,  g_wscores);
    cudaGetSymbolAddress((void**)&ssc,  g_sscores);
    cudaGetSymbolAddress((void**)&sat,  g_sattn);
    cudaGetSymbolAddress((void**)&cat,  g_cat);
    cudaGetSymbolAddress((void**)&hid,  g_hid);
    cudaGetSymbolAddress((void**)&pg,   g_pgen);
    cudaGetSymbolAddress((void**)&lg,   g_logits);

    // 1. embedding + GRU gates + combine
    embed_kernel<<<BB, EMB_>>>(emb, y, yemb);
    gemm_bias_kernel<<<dim3(24, 2), 256>>>(yemb, gwih, gbih, gi, BB, 3 * HH, EMB_);
    gemm_bias_kernel<<<dim3(24, 2), 256>>>(h0,   gwhh, gbhh, gh, BB, 3 * HH, HH);
    gru_kernel<<<(BB * HH + 255) / 256, 256>>>(gi, gh, h0, hl, cat, out + OUT_H);

    // 2. decoder-state projections for both attentions
    gemm_bias_kernel<<<dim3(8, 2), 256>>>(hl, wdpw, wdpb, dpw, BB, HH, HH);
    gemm_bias_kernel<<<dim3(8, 2), 256>>>(hl, sdpw, sdpb, dps, BB, HH, HH);

    // 3. fused attention scores (tensor cores, bf16x3)
    attn_scores_mma<true ><<<(BB * LW) / 64, 256>>>(wmem, wmp, dpw, wv, wcp, cov, wsc, LW);
    attn_scores_mma<false><<<(BB * SSL) / 64, 256>>>(smem_bank, smp, dps, sv, nullptr, nullptr, ssc, SSL);

    // 4. softmax + mask + renorm (+ coverage output for word)
    softmax_mask_kernel<<<BB, 128>>>(wsc, wmask, cov, out + OUT_WATTN, out + OUT_WCOV, LW);
    softmax_mask_kernel<<<BB, 128>>>(ssc, smask, nullptr, sat, nullptr, SSL);

    // 5. contexts (into cat buffer; word_ctx also to output)
    context_kernel<<<dim3(BB, 4), 128>>>(out + OUT_WATTN, wmem, out + OUT_WCTX, cat, LW, 0);
    context_kernel<<<dim3(BB, 4), 128>>>(sat, smem_bank, nullptr, cat, SSL, 512);

    // 6. p_gen
    pgen_kernel<<<BB, 256>>>(cat, yemb, pgw, pgb, pg, out + OUT_PGEN);

    // 7. vocab head: hid then logits (logits on tensor cores)
    gemm_bias_kernel<<<dim3(8, 2), 256>>>(cat, vd1w, vd1b, hid, BB, HH, 3 * HH);
    mma_gemm_bias<<<dim3((VV + 63) / 64, 2), 256>>>(hid, vd2w, vd2b, lg, BB, VV, HH);

    // 8. vocab softmax, p_gen mix, zeros for OOV slots, scatter-add of copy dist
    final_kernel<<<BB, 256>>>(lg, pg, out + OUT_WATTN, soov, out + OUT_FINAL);
}